// round 8
// baseline (speedup 1.0000x reference)
#include <cuda_runtime.h>
#include <cuda_bf16.h>
#include <math.h>

#define N_NODES 100000
#define N_EDGES 3200000
#define LD      6
#define HID     16
#define LL      8
#define DIN     24
#define EPS     1e-6f

#define EB ((N_EDGES + 255) / 256)
#define NB ((N_NODES + 255) / 256)
#define WPB 8                      // warps per block in layer kernel
#define LGRID ((N_NODES + WPB - 1) / WPB)

// ---------------- scratch (device globals; no allocations allowed) ----------
__device__ int2   g_eidx [N_EDGES];        // (src,dst) original order (flows)
__device__ int    g_degi [N_NODES];
__device__ int    g_off  [N_NODES + 1];    // CSR row offsets (by dst)
__device__ int    g_cur  [N_NODES];        // scatter cursors
__device__ int    g_bsum [NB];             // block partial sums for scan
__device__ int    g_bbase[NB];             // scanned block bases
__device__ int    g_srccsr[N_EDGES];       // src per CSR slot
__device__ float4 g_eacsr [N_EDGES];       // edge_attr per CSR slot
__device__ float4 g_S0[N_NODES * 4];       // ping-pong S/D (16 floats per node)
__device__ float4 g_D0[N_NODES * 4];
__device__ float4 g_S1[N_NODES * 4];
__device__ float4 g_D1[N_NODES * 4];
__device__ float  g_Pfix[N_NODES];
__device__ float  g_bal [N_NODES];
__device__ double g_sum;

// ---------------- prep: pack indices + integer degree ------------------------
__global__ void __launch_bounds__(256) prep_i32(const int* __restrict__ ei) {
    int e = blockIdx.x * 256 + threadIdx.x;
    if (e >= N_EDGES) return;
    int s = ei[e];
    int d = ei[N_EDGES + e];
    g_eidx[e] = make_int2(s, d);
    atomicAdd(&g_degi[d], 1);
}
__global__ void __launch_bounds__(256) prep_i64(const long long* __restrict__ ei) {
    int e = blockIdx.x * 256 + threadIdx.x;
    if (e >= N_EDGES) return;
    int s = (int)ei[e];
    int d = (int)ei[N_EDGES + e];
    g_eidx[e] = make_int2(s, d);
    atomicAdd(&g_degi[d], 1);
}

// ---------------- 3-step exclusive scan of degrees ---------------------------
__global__ void __launch_bounds__(256) scan_block() {
    __shared__ int sh[256];
    int t = threadIdx.x;
    int i = blockIdx.x * 256 + t;
    int v = (i < N_NODES) ? g_degi[i] : 0;
    sh[t] = v;
    __syncthreads();
    #pragma unroll
    for (int o = 1; o < 256; o <<= 1) {
        int u = (t >= o) ? sh[t - o] : 0;
        __syncthreads();
        sh[t] += u;
        __syncthreads();
    }
    if (i < N_NODES) g_off[i] = sh[t] - v;      // block-local exclusive
    if (t == 255) g_bsum[blockIdx.x] = sh[255];
}
__global__ void __launch_bounds__(512) scan_bsums() {
    __shared__ int sh[512];
    int t = threadIdx.x;
    int v = (t < NB) ? g_bsum[t] : 0;
    sh[t] = v;
    __syncthreads();
    #pragma unroll
    for (int o = 1; o < 512; o <<= 1) {
        int u = (t >= o) ? sh[t - o] : 0;
        __syncthreads();
        sh[t] += u;
        __syncthreads();
    }
    if (t < NB) g_bbase[t] = sh[t] - v;          // exclusive
}
__global__ void __launch_bounds__(256) scan_add() {
    int i = blockIdx.x * 256 + threadIdx.x;
    if (i < N_NODES) g_off[i] += g_bbase[blockIdx.x];
    if (i == 0) g_off[N_NODES] = N_EDGES;
}

// ---------------- CSR scatter ------------------------------------------------
__global__ void __launch_bounds__(256) scatter_kernel(const float4* __restrict__ ea4) {
    int e = blockIdx.x * 256 + threadIdx.x;
    if (e >= N_EDGES) return;
    int2 sd = g_eidx[e];
    int pos = g_off[sd.y] + atomicAdd(&g_cur[sd.y], 1);
    g_srccsr[pos] = sd.x;
    g_eacsr[pos]  = ea4[e];
}

// ---------------- init S0/D0 (X = 0, x terms only) ----------------------------
__global__ void __launch_bounds__(256) init_kernel(
    const float* __restrict__ x,
    const float* __restrict__ W1, const float* __restrict__ b1)
{
    __shared__ float sW1[DIN * HID];
    __shared__ float sb1[HID];
    int t = threadIdx.x;
    for (int i = t; i < DIN * HID; i += 256) sW1[i] = W1[i];   // layer 0
    if (t < HID) sb1[t] = b1[t];
    __syncthreads();

    int n = blockIdx.x * 256 + t;
    if (n >= N_NODES) return;
    float4 xv = ((const float4*)x)[n];
    float sv[HID], dv[HID];
    #pragma unroll
    for (int j = 0; j < HID; j++) {
        sv[j] = xv.x*sW1[12*HID+j] + xv.y*sW1[13*HID+j] + xv.z*sW1[14*HID+j] + xv.w*sW1[15*HID+j];
        dv[j] = sb1[j]
              + xv.x*sW1[16*HID+j] + xv.y*sW1[17*HID+j] + xv.z*sW1[18*HID+j] + xv.w*sW1[19*HID+j];
    }
    #pragma unroll
    for (int q = 0; q < 4; q++) {
        g_S0[(size_t)n*4+q] = make_float4(sv[q*4], sv[q*4+1], sv[q*4+2], sv[q*4+3]);
        g_D0[(size_t)n*4+q] = make_float4(dv[q*4], dv[q*4+1], dv[q*4+2], dv[q*4+3]);
    }
}

// ---------------- fused layer kernel (warp per dst node) ----------------------
// Reads S/D of layer l; aggregates over in-edges (CSR); computes X=relu(agg);
// writes S/D of layer l+1 (mode 0) or P/Pfix/bal (mode 1 = last layer).
__global__ void __launch_bounds__(256) layer_kernel(
    const float4* __restrict__ Sin, const float4* __restrict__ Din,
    float* __restrict__ Sout, float* __restrict__ Dout,
    const float* __restrict__ x,
    const float* __restrict__ W1all, const float* __restrict__ b1all,
    const float* __restrict__ W2all, const float* __restrict__ b2all,
    const float* __restrict__ Wf,    const float* __restrict__ bf,
    float* __restrict__ outP, int l, int mode)
{
    __shared__ float sW1e[4 * HID];     // layer l, rows 20..23
    __shared__ float sW2 [HID * LD];    // layer l
    __shared__ float sb2 [LD];
    __shared__ float sW1n[20 * HID];    // layer l+1, rows 0..19
    __shared__ float sb1n[HID];
    __shared__ float sWf [LD];
    __shared__ float sbf;

    int t = threadIdx.x;
    if (t < 4 * HID) sW1e[t] = W1all[l * DIN * HID + 20 * HID + t];
    for (int i = t; i < HID * LD; i += 256) sW2[i] = W2all[l * HID * LD + i];
    if (t < LD) sb2[t] = b2all[l * LD + t];
    if (mode == 0) {
        for (int i = t; i < 20 * HID; i += 256) sW1n[i] = W1all[(l + 1) * DIN * HID + i];
        if (t < HID) sb1n[t] = b1all[(l + 1) * HID + t];
    } else {
        if (t < LD) sWf[t] = Wf[t];
        if (t == 0) sbf = bf[0];
    }
    __syncthreads();

    int wid  = blockIdx.x * WPB + (t >> 5);
    int lane = t & 31;
    if (wid >= N_NODES) return;

    // D[dst]: broadcast loads (all lanes same address)
    float Dv[HID];
    #pragma unroll
    for (int q = 0; q < 4; q++) {
        float4 d4 = Din[(size_t)wid * 4 + q];
        Dv[q*4+0] = d4.x; Dv[q*4+1] = d4.y; Dv[q*4+2] = d4.z; Dv[q*4+3] = d4.w;
    }

    int start = __ldg(&g_off[wid]);
    int end   = __ldg(&g_off[wid + 1]);
    float acc0 = 0.f, acc1 = 0.f, acc2 = 0.f, acc3 = 0.f, acc4 = 0.f, acc5 = 0.f;

    for (int i = start + lane; i < end; i += 32) {
        int s = g_srccsr[i];
        float4 ea = g_eacsr[i];
        float Sv[HID];
        #pragma unroll
        for (int q = 0; q < 4; q++) {
            float4 s4 = Sin[(size_t)s * 4 + q];
            Sv[q*4+0] = s4.x; Sv[q*4+1] = s4.y; Sv[q*4+2] = s4.z; Sv[q*4+3] = s4.w;
        }
        #pragma unroll
        for (int j = 0; j < HID; j++) {
            float v = Sv[j] + Dv[j];
            v += ea.x * sW1e[0*HID + j];
            v += ea.y * sW1e[1*HID + j];
            v += ea.z * sW1e[2*HID + j];
            v += ea.w * sW1e[3*HID + j];
            float h = fmaxf(v, 0.0f);
            acc0 += h * sW2[j*LD + 0];
            acc1 += h * sW2[j*LD + 1];
            acc2 += h * sW2[j*LD + 2];
            acc3 += h * sW2[j*LD + 3];
            acc4 += h * sW2[j*LD + 4];
            acc5 += h * sW2[j*LD + 5];
        }
    }

    // butterfly reduce -> all lanes hold totals
    #pragma unroll
    for (int o = 16; o > 0; o >>= 1) {
        acc0 += __shfl_xor_sync(0xFFFFFFFF, acc0, o);
        acc1 += __shfl_xor_sync(0xFFFFFFFF, acc1, o);
        acc2 += __shfl_xor_sync(0xFFFFFFFF, acc2, o);
        acc3 += __shfl_xor_sync(0xFFFFFFFF, acc3, o);
        acc4 += __shfl_xor_sync(0xFFFFFFFF, acc4, o);
        acc5 += __shfl_xor_sync(0xFFFFFFFF, acc5, o);
    }

    int deg = end - start;
    float inv = (deg > 0) ? 1.0f / (float)deg : 0.0f;
    float X[LD];
    X[0] = (deg > 0) ? fmaxf(acc0 * inv + sb2[0], 0.f) : 0.f;
    X[1] = (deg > 0) ? fmaxf(acc1 * inv + sb2[1], 0.f) : 0.f;
    X[2] = (deg > 0) ? fmaxf(acc2 * inv + sb2[2], 0.f) : 0.f;
    X[3] = (deg > 0) ? fmaxf(acc3 * inv + sb2[3], 0.f) : 0.f;
    X[4] = (deg > 0) ? fmaxf(acc4 * inv + sb2[4], 0.f) : 0.f;
    X[5] = (deg > 0) ? fmaxf(acc5 * inv + sb2[5], 0.f) : 0.f;

    if (mode == 0) {
        if (lane < HID) {
            int j = lane;
            float4 xv = ((const float4*)x)[wid];
            float a = 0.f, c = sb1n[j];
            #pragma unroll
            for (int i = 0; i < LD; i++) {
                a += X[i] * sW1n[i * HID + j];
                c += X[i] * sW1n[(LD + i) * HID + j];
            }
            a += xv.x*sW1n[12*HID+j] + xv.y*sW1n[13*HID+j] + xv.z*sW1n[14*HID+j] + xv.w*sW1n[15*HID+j];
            c += xv.x*sW1n[16*HID+j] + xv.y*sW1n[17*HID+j] + xv.z*sW1n[18*HID+j] + xv.w*sW1n[19*HID+j];
            Sout[(size_t)wid * HID + j] = a;
            Dout[(size_t)wid * HID + j] = c;
        }
    } else {
        if (lane == 0) {
            float p = sbf;
            #pragma unroll
            for (int i = 0; i < LD; i++) p += X[i] * sWf[i];
            p = fmaxf(p, 0.0f);
            outP[wid] = p;
            float4 xv = ((const float4*)x)[wid];
            g_Pfix[wid] = (xv.w != 0.0f) ? xv.w : p;
            g_bal[wid]  = xv.x;
        }
    }
}

// ---------------- flows + balance --------------------------------------------
__global__ void __launch_bounds__(256) flows_kernel(
    const float4* __restrict__ ea4,
    float* __restrict__ out_flows)
{
    int e = blockIdx.x * 256 + threadIdx.x;
    if (e >= N_EDGES) return;
    int2 sd = g_eidx[e];
    float ps = g_Pfix[sd.x];
    float pd = g_Pfix[sd.y];
    float dp2 = ps * ps - pd * pd;
    float k = ea4[e].x;
    float sg = (dp2 > 0.0f) ? 1.0f : ((dp2 < 0.0f) ? -1.0f : 0.0f);
    float f = sg * sqrtf(fabsf(dp2) / k + EPS);
    out_flows[e] = f;
    atomicAdd(&g_bal[sd.y], f);
    atomicAdd(&g_bal[sd.x], -f);
}

// ---------------- imbalance reduction -----------------------------------------
__global__ void __launch_bounds__(256) reduce_kernel() {
    __shared__ double sh[256];
    int n = blockIdx.x * 256 + threadIdx.x;
    double v = 0.0;
    if (n < N_NODES) {
        double b = (double)g_bal[n];
        v = b * b;
    }
    sh[threadIdx.x] = v;
    __syncthreads();
    for (int s = 128; s > 0; s >>= 1) {
        if (threadIdx.x < s) sh[threadIdx.x] += sh[threadIdx.x + s];
        __syncthreads();
    }
    if (threadIdx.x == 0) atomicAdd(&g_sum, sh[0]);
}

__global__ void final_kernel(float* __restrict__ out) {
    out[0] = (float)sqrt(g_sum);
}

// ---------------- launch -------------------------------------------------------
extern "C" void kernel_launch(void* const* d_in, const int* in_sizes, int n_in,
                              void* d_out, int out_size)
{
    const float*  x   = (const float*)d_in[0];
    const float4* ea4 = (const float4*)d_in[1];
    const void*   ei  = d_in[2];
    const float*  W1  = (const float*)d_in[3];
    const float*  b1  = (const float*)d_in[4];
    const float*  W2  = (const float*)d_in[5];
    const float*  b2  = (const float*)d_in[6];
    const float*  Wf  = (const float*)d_in[7];
    const float*  bf  = (const float*)d_in[8];
    float* out = (float*)d_out;

    static void *p_degi = nullptr, *p_cur = nullptr, *p_sum = nullptr;
    static float4 *pS0, *pD0, *pS1, *pD1;
    if (!p_degi) {
        cudaGetSymbolAddress(&p_degi, g_degi);
        cudaGetSymbolAddress(&p_cur,  g_cur);
        cudaGetSymbolAddress(&p_sum,  g_sum);
        void* tmp;
        cudaGetSymbolAddress(&tmp, g_S0); pS0 = (float4*)tmp;
        cudaGetSymbolAddress(&tmp, g_D0); pD0 = (float4*)tmp;
        cudaGetSymbolAddress(&tmp, g_S1); pS1 = (float4*)tmp;
        cudaGetSymbolAddress(&tmp, g_D1); pD1 = (float4*)tmp;
    }

    cudaMemsetAsync(p_degi, 0, N_NODES * sizeof(int));
    cudaMemsetAsync(p_cur,  0, N_NODES * sizeof(int));
    cudaMemsetAsync(p_sum,  0, sizeof(double));

    if (in_sizes[2] == 2 * N_EDGES) prep_i32<<<EB, 256>>>((const int*)ei);
    else                            prep_i64<<<EB, 256>>>((const long long*)ei);

    scan_block<<<NB, 256>>>();
    scan_bsums<<<1, 512>>>();
    scan_add<<<NB, 256>>>();
    scatter_kernel<<<EB, 256>>>(ea4);
    init_kernel<<<NB, 256>>>(x, W1, b1);

    for (int l = 0; l < LL; l++) {
        const float4* Sin = (l & 1) ? pS1 : pS0;
        const float4* Din = (l & 1) ? pD1 : pD0;
        float* Sout = (float*)((l & 1) ? pS0 : pS1);
        float* Dout = (float*)((l & 1) ? pD0 : pD1);
        layer_kernel<<<LGRID, 256>>>(Sin, Din, Sout, Dout, x,
                                     W1, b1, W2, b2, Wf, bf,
                                     out, l, (l == LL - 1) ? 1 : 0);
    }

    flows_kernel<<<EB, 256>>>(ea4, out + N_NODES);
    reduce_kernel<<<NB, 256>>>();
    final_kernel<<<1, 1>>>(out + N_NODES + N_EDGES);
}